// round 3
// baseline (speedup 1.0000x reference)
#include <cuda_runtime.h>
#include <stdint.h>

// Problem constants
#define NDIM 2048   // tokens
#define CDIM 2048   // channels
#define HEADS 16
#define HDIM 128
#define TSTEPS 10

// Scratch: spike masks (10-bit per element) for {pos,neg} x {q,k,v}, and the
// T-averaged attention output Xm (pre output-GEMM).
// masks[0..2] = pos q,k,v ; masks[3..5] = neg q,k,v
__device__ unsigned short g_masks[6][NDIM * CDIM];   // 48 MB
__device__ float g_xm[NDIM * CDIM];                  // 16 MB

// ---------------------------------------------------------------------------
// Tiled fp32 GEMM: C = A @ B, 2048^3. BM=BN=128, BK=16, 256 threads, 8x8/thr.
// SPIKE=true : A = relu(+/- x) applied on load (branch = blockIdx.z/3),
//              B selected from {wq,wk,wv} by blockIdx.z%3,
//              epilogue = 10-step IF scan -> uint16 spike mask.
// SPIKE=false: A = g_xm, B = B0 (wo), epilogue = plain float store to Cout.
// ---------------------------------------------------------------------------
template <bool SPIKE>
__global__ __launch_bounds__(256) void gemm_k(const float* __restrict__ Aarg,
                                              const float* __restrict__ B0,
                                              const float* __restrict__ B1,
                                              const float* __restrict__ B2,
                                              float* __restrict__ Cout) {
    const int tid = threadIdx.x;
    const int bm = blockIdx.y;
    const int bn = blockIdx.x;

    int branch = 0;
    int wsel = 0;
    const float* Bp = B0;
    const float* A = Aarg;
    if (SPIKE) {
        wsel = blockIdx.z % 3;
        branch = blockIdx.z / 3;
        Bp = (wsel == 0) ? B0 : ((wsel == 1) ? B1 : B2);
    } else {
        A = g_xm;
    }

    __shared__ float As[16][128];   // transposed A tile: As[k][m]
    __shared__ float Bs[16][128];   // Bs[k][n]

    float acc[8][8];
#pragma unroll
    for (int i = 0; i < 8; ++i)
#pragma unroll
        for (int j = 0; j < 8; ++j) acc[i][j] = 0.f;

    const int ty = tid >> 4;        // 0..15
    const int tx = tid & 15;        // 0..15

    const int aRow = tid >> 2;      // 0..63
    const int aCol = (tid & 3) * 4; // 0,4,8,12
    const int bRow = tid >> 5;      // 0..7
    const int bCol = (tid & 31) * 4;// 0..124

    const float* Abase = A + (size_t)(bm * 128) * CDIM;

    for (int kt = 0; kt < CDIM; kt += 16) {
        // Load A tile (128 x 16), transpose into As[k][m], relu applied here.
#pragma unroll
        for (int r = 0; r < 128; r += 64) {
            float4 a = *(const float4*)(Abase + (size_t)(aRow + r) * CDIM + kt + aCol);
            if (SPIKE) {
                if (branch) {
                    a.x = fmaxf(-a.x, 0.f); a.y = fmaxf(-a.y, 0.f);
                    a.z = fmaxf(-a.z, 0.f); a.w = fmaxf(-a.w, 0.f);
                } else {
                    a.x = fmaxf(a.x, 0.f); a.y = fmaxf(a.y, 0.f);
                    a.z = fmaxf(a.z, 0.f); a.w = fmaxf(a.w, 0.f);
                }
            }
            As[aCol + 0][aRow + r] = a.x;
            As[aCol + 1][aRow + r] = a.y;
            As[aCol + 2][aRow + r] = a.z;
            As[aCol + 3][aRow + r] = a.w;
        }
        // Load B tile (16 x 128)
#pragma unroll
        for (int r = 0; r < 16; r += 8) {
            float4 b = *(const float4*)(Bp + (size_t)(kt + bRow + r) * CDIM + bn * 128 + bCol);
            *(float4*)&Bs[bRow + r][bCol] = b;
        }
        __syncthreads();

#pragma unroll
        for (int k = 0; k < 16; ++k) {
            float ra[8], rb[8];
#pragma unroll
            for (int i = 0; i < 8; ++i) ra[i] = As[k][ty * 8 + i];
#pragma unroll
            for (int j = 0; j < 8; ++j) rb[j] = Bs[k][tx * 8 + j];
#pragma unroll
            for (int i = 0; i < 8; ++i)
#pragma unroll
                for (int j = 0; j < 8; ++j)
                    acc[i][j] = fmaf(ra[i], rb[j], acc[i][j]);
        }
        __syncthreads();
    }

    // Epilogue
    if (SPIKE) {
        unsigned short* Mo = g_masks[branch * 3 + wsel];
#pragma unroll
        for (int i = 0; i < 8; ++i) {
            const int row = bm * 128 + ty * 8 + i;
#pragma unroll
            for (int j = 0; j < 8; ++j) {
                const int col = bn * 128 + tx * 8 + j;
                float y = acc[i][j];
                // 10-step IF neuron: v += y; spike if v>=1; hard reset v=0.
                float v = 0.f;
                unsigned m = 0;
#pragma unroll
                for (int t = 0; t < TSTEPS; ++t) {
                    v += y;
                    if (v >= 1.0f) { m |= (1u << t); v = 0.f; }
                }
                Mo[(size_t)row * CDIM + col] = (unsigned short)m;
            }
        }
    } else {
#pragma unroll
        for (int i = 0; i < 8; ++i) {
            const int row = bm * 128 + ty * 8 + i;
#pragma unroll
            for (int j = 0; j < 8; ++j) {
                const int col = bn * 128 + tx * 8 + j;
                Cout[(size_t)row * CDIM + col] = acc[i][j];
            }
        }
    }
}

// ---------------------------------------------------------------------------
// Per-token spiking attention. One block per token n (2048 blocks, 256 thr).
// xq_t = qp_t - qn_t in {-1,0,1}. attn_t = Q_t K_t^T (int), out += attn_t V_t.
// Result Xm[n][d*16+h] = acc * (0.125/10)  (transpose(-1,-2) + scale + T-mean)
// ---------------------------------------------------------------------------
__global__ __launch_bounds__(256) void attn_k() {
    const int n = blockIdx.x;
    const int tid = threadIdx.x;

    __shared__ unsigned short Mp[3][CDIM];
    __shared__ unsigned short Mn[3][CDIM];
    __shared__ __align__(16) int8_t Qt[CDIM];
    __shared__ __align__(16) int8_t Kt[CDIM];
    __shared__ __align__(16) int8_t Vt[CDIM];
    __shared__ int attn_s[HEADS * HEADS];

    const size_t base = (size_t)n * CDIM;
    for (int c = tid; c < CDIM; c += 256) {
        Mp[0][c] = g_masks[0][base + c];
        Mp[1][c] = g_masks[1][base + c];
        Mp[2][c] = g_masks[2][base + c];
        Mn[0][c] = g_masks[3][base + c];
        Mn[1][c] = g_masks[4][base + c];
        Mn[2][c] = g_masks[5][base + c];
    }
    __syncthreads();

    int acc[8];
#pragma unroll
    for (int j = 0; j < 8; ++j) acc[j] = 0;

    const int h = tid >> 4;            // output head this thread owns
    const int dbase = (tid & 15) * 8;  // 8 consecutive d per thread

    for (int t = 0; t < TSTEPS; ++t) {
        // Build ternary int8 matrices (flat index c == h*128+d)
        for (int c = tid; c < CDIM; c += 256) {
            Qt[c] = (int8_t)(((Mp[0][c] >> t) & 1) - ((Mn[0][c] >> t) & 1));
            Kt[c] = (int8_t)(((Mp[1][c] >> t) & 1) - ((Mn[1][c] >> t) & 1));
            Vt[c] = (int8_t)(((Mp[2][c] >> t) & 1) - ((Mn[2][c] >> t) & 1));
        }
        __syncthreads();

        // attn[h][m] = sum_d Q[h][d]*K[m][d] via dp4a; rotate word index by
        // 2*m to avoid 16-way smem bank conflicts on the K rows.
        {
            const int hh = tid >> 4;
            const int mm = tid & 15;
            const int* qr = (const int*)(Qt + hh * 128);
            const int* kr = (const int*)(Kt + mm * 128);
            const int rot = (mm * 2) & 31;
            int s = 0;
#pragma unroll
            for (int w = 0; w < 32; ++w) {
                const int wi = (w + rot) & 31;
                s = __dp4a(qr[wi], kr[wi], s);
            }
            attn_s[hh * 16 + mm] = s;
        }
        __syncthreads();

        // out[h][dbase..dbase+7] += sum_m attn[h][m] * V[m][d]
#pragma unroll
        for (int m = 0; m < HEADS; ++m) {
            const int a = attn_s[h * 16 + m];
            const int8_t* vp = Vt + m * 128 + dbase;
#pragma unroll
            for (int j = 0; j < 8; ++j) acc[j] += a * (int)vp[j];
        }
        __syncthreads();  // protect Qt/Kt/Vt before next-t rebuild
    }

    // Write Xm with channel transpose: c' = d*HEADS + h ; scale 0.125/10
#pragma unroll
    for (int j = 0; j < 8; ++j)
        g_xm[base + (size_t)(dbase + j) * HEADS + h] = (float)acc[j] * 0.0125f;
}

// ---------------------------------------------------------------------------
extern "C" void kernel_launch(void* const* d_in, const int* in_sizes, int n_in,
                              void* d_out, int out_size) {
    const float* x  = (const float*)d_in[0];
    // d_in[1] = freqs_cis (unused by the forward)
    const float* wq = (const float*)d_in[2];
    const float* wk = (const float*)d_in[3];
    const float* wv = (const float*)d_in[4];
    const float* wo = (const float*)d_in[5];
    float* out = (float*)d_out;

    // 6 pre-GEMMs ({pos,neg} x {q,k,v}) with fused relu + IF-spike epilogue
    gemm_k<true><<<dim3(16, 16, 6), 256>>>(x, wq, wk, wv, nullptr);
    // per-token ternary attention, T-mean folded in
    attn_k<<<NDIM, 256>>>();
    // output GEMM: out = Xm @ wo
    gemm_k<false><<<dim3(16, 16, 1), 256>>>(x, wo, nullptr, nullptr, out);
}

// round 12
// speedup vs baseline: 1.3245x; 1.3245x over previous
#include <cuda_runtime.h>
#include <cuda_bf16.h>
#include <stdint.h>

#define NDIM 2048
#define CDIM 2048
#define HEADS 16
#define TSTEPS 10

#define NCHUNK 32
#define BKC    64
#define TILEB  16384
#define STAGEB (6 * TILEB)
#define CTRLB  1024
#define SMEM_TOTAL (CTRLB + 2 * STAGEB)

// idesc kind::f16, bf16 x bf16 -> f32, M=128, N=64
#define IDESC 0x8100490u

// Emulation y-error is empirically BOUNDED < ~4e-4 (delta-independence of the
// R10/R11 residual). DELTA=5e-4 catches every noise flip; IF boundaries
// (y=1/m) are >= 1/90 apart >> 2*DELTA so the proof mask(y-D)==mask(y+D) holds.
#define DELTA 5e-4f
#define FLAG_CAP (1u << 22)

#if defined(__CUDA_ARCH__) && \
    (defined(__CUDA_ARCH_FEAT_SM103_ALL) || defined(__CUDA_ARCH_FEAT_SM100_ALL) || \
     defined(__CUDA_ARCH_SPECIFIC__))
#define TC_OK 1
#else
#define TC_OK 0
#endif

// ---------------------------------------------------------------------------
// Global scratch
// ---------------------------------------------------------------------------
__device__ __align__(256) unsigned short g_masks[6][NDIM * CDIM];      // 48 MB
__device__ __align__(256) __nv_bfloat16 g_as[2][3][NDIM * CDIM];       // 48 MB
__device__ __align__(256) __nv_bfloat16 g_ws[4][3][CDIM * CDIM];       // 96 MB
__device__ __align__(256) float g_wt[3][CDIM * CDIM];                  // 48 MB fp32 wT (repair)
__device__ __align__(256) __nv_bfloat16 g_xms[3][NDIM * CDIM];         // 24 MB
__device__ unsigned g_flagcnt;
__device__ unsigned g_flags[FLAG_CAP];                                 // 16 MB

// ---------------------------------------------------------------------------
__device__ __forceinline__ void split3(float a, __nv_bfloat16& h0, __nv_bfloat16& h1,
                                       __nv_bfloat16& h2) {
    h0 = __float2bfloat16_rn(a);
    float r = a - __bfloat162float(h0);
    h1 = __float2bfloat16_rn(r);
    r -= __bfloat162float(h1);
    h2 = __float2bfloat16_rn(r);
}

__device__ __forceinline__ unsigned if_scan_mask(float y) {
    float v = 0.f;
    unsigned m = 0;
#pragma unroll
    for (int t = 0; t < TSTEPS; ++t) {
        v += y;
        if (v >= 1.0f) { m |= (1u << t); v = 0.f; }
    }
    return m;
}

// Provably-correct mask when the DELTA-interval crosses no IF boundary; else
// flag (z,row,col) for exact sequential-order fp32 repair. Warp-aggregated
// atomic; must be called by all 32 lanes of the warp together.
__device__ __forceinline__ unsigned mask_or_flag(float y, unsigned enc) {
    const unsigned mlo = if_scan_mask(y - DELTA);
    const unsigned mhi = if_scan_mask(y + DELTA);
    const bool flag = (mlo != mhi);
    const unsigned bal = __ballot_sync(0xFFFFFFFFu, flag);
    if (bal) {
        const int lane = threadIdx.x & 31;
        const int leader = __ffs(bal) - 1;
        unsigned base = 0;
        if (lane == leader) base = atomicAdd(&g_flagcnt, (unsigned)__popc(bal));
        base = __shfl_sync(0xFFFFFFFFu, base, leader);
        if (flag) {
            const unsigned off = (unsigned)__popc(bal & ((1u << lane) - 1u));
            if (base + off < FLAG_CAP) g_flags[base + off] = enc;
        }
    }
    return mlo;
}

#if TC_OK
// ---------------------------------------------------------------------------
// tcgen05-path PTX helpers
// ---------------------------------------------------------------------------
__device__ __forceinline__ uint32_t smem_u32(const void* p) {
    return (uint32_t)__cvta_generic_to_shared(p);
}
__device__ __forceinline__ uint32_t elect1() {
    uint32_t pred;
    asm volatile("{\n\t.reg .pred p;\n\telect.sync _|p, 0xFFFFFFFF;\n\t"
                 "selp.b32 %0, 1, 0, p;\n\t}" : "=r"(pred));
    return pred;
}
__device__ __forceinline__ uint64_t mkdesc(uint32_t addr) {
    return 0x4000404000010000ULL | (uint64_t)((addr >> 4) & 0x3FFF);
}
__device__ __forceinline__ void mma_ss(uint32_t d, uint64_t ad, uint64_t bd, uint32_t en) {
    asm volatile(
        "{\n\t.reg .pred p;\n\tsetp.ne.u32 p, %5, 0;\n\t"
        "tcgen05.mma.cta_group::1.kind::f16 [%0], %1, %2, %3, {%4, %4, %4, %4}, p;\n\t}"
        :: "r"(d), "l"(ad), "l"(bd), "r"(IDESC), "r"(0u), "r"(en) : "memory");
}
__device__ __forceinline__ void mbwait(uint32_t mb, int phase) {
    asm volatile(
        "{\n\t.reg .pred P;\n\tWL%=:\n\t"
        "mbarrier.try_wait.parity.acquire.cta.shared::cta.b64 P, [%0], %1, 0x989680;\n\t"
        "@P bra.uni WD%=;\n\tbra.uni WL%=;\n\tWD%=:\n\t}"
        :: "r"(mb), "r"(phase) : "memory");
}
#define LDTM32(r, addr) \
    asm volatile( \
        "tcgen05.ld.sync.aligned.32x32b.x32.b32 " \
        "{%0, %1, %2, %3, %4, %5, %6, %7, " \
        " %8, %9, %10, %11, %12, %13, %14, %15, " \
        " %16, %17, %18, %19, %20, %21, %22, %23, " \
        " %24, %25, %26, %27, %28, %29, %30, %31}, [%32];" \
        : "=r"((r)[0]),  "=r"((r)[1]),  "=r"((r)[2]),  "=r"((r)[3]), \
          "=r"((r)[4]),  "=r"((r)[5]),  "=r"((r)[6]),  "=r"((r)[7]), \
          "=r"((r)[8]),  "=r"((r)[9]),  "=r"((r)[10]), "=r"((r)[11]), \
          "=r"((r)[12]), "=r"((r)[13]), "=r"((r)[14]), "=r"((r)[15]), \
          "=r"((r)[16]), "=r"((r)[17]), "=r"((r)[18]), "=r"((r)[19]), \
          "=r"((r)[20]), "=r"((r)[21]), "=r"((r)[22]), "=r"((r)[23]), \
          "=r"((r)[24]), "=r"((r)[25]), "=r"((r)[26]), "=r"((r)[27]), \
          "=r"((r)[28]), "=r"((r)[29]), "=r"((r)[30]), "=r"((r)[31]) \
        : "r"(addr))
#endif  // TC_OK

// ---------------------------------------------------------------------------
__global__ void reset_flags() { g_flagcnt = 0; }

// prep_x: relu(+/-x) -> 3 bf16 splits each.
__global__ __launch_bounds__(256) void prep_x(const float* __restrict__ x) {
    const int i = blockIdx.x * 256 + threadIdx.x;
    float4 v = ((const float4*)x)[i];
    float p[4] = {fmaxf(v.x, 0.f), fmaxf(v.y, 0.f), fmaxf(v.z, 0.f), fmaxf(v.w, 0.f)};
    float n[4] = {fmaxf(-v.x, 0.f), fmaxf(-v.y, 0.f), fmaxf(-v.z, 0.f), fmaxf(-v.w, 0.f)};
    union U { __nv_bfloat16 h[4]; uint2 u; };
    U sp[3], sn[3];
#pragma unroll
    for (int e = 0; e < 4; ++e) {
        split3(p[e], sp[0].h[e], sp[1].h[e], sp[2].h[e]);
        split3(n[e], sn[0].h[e], sn[1].h[e], sn[2].h[e]);
    }
#pragma unroll
    for (int s = 0; s < 3; ++s) {
        ((uint2*)g_as[0][s])[i] = sp[s].u;
        ((uint2*)g_as[1][s])[i] = sn[s].u;
    }
}

// prep_w: transpose + split wq,wk,wv,wo; also fp32 wT for q,k,v (repair).
__global__ __launch_bounds__(256) void prep_w(const float* __restrict__ wq,
                                              const float* __restrict__ wk,
                                              const float* __restrict__ wv,
                                              const float* __restrict__ wo) {
    const int z = blockIdx.z;
    const float* w = (z == 0) ? wq : (z == 1) ? wk : (z == 2) ? wv : wo;
    __shared__ float tile[32][33];
    const int tx = threadIdx.x, ty = threadIdx.y;
    const int nBase = blockIdx.x * 32, kBase = blockIdx.y * 32;
#pragma unroll
    for (int i = 0; i < 4; ++i)
        tile[ty + i * 8][tx] = w[(size_t)(kBase + ty + i * 8) * CDIM + nBase + tx];
    __syncthreads();
#pragma unroll
    for (int i = 0; i < 4; ++i) {
        float v = tile[tx][ty + i * 8];
        __nv_bfloat16 h0, h1, h2;
        split3(v, h0, h1, h2);
        const size_t o = (size_t)(nBase + ty + i * 8) * CDIM + kBase + tx;
        g_ws[z][0][o] = h0;
        g_ws[z][1][o] = h1;
        g_ws[z][2][o] = h2;
        if (z < 3) g_wt[z][o] = v;
    }
}

// ---------------------------------------------------------------------------
// tcgen05 bf16x6 emulated GEMM; SPIKE: IF epilogue with delta-flagging.
// ---------------------------------------------------------------------------
template <bool SPIKE>
__global__ __launch_bounds__(256, 1) void gemm_tc(float* __restrict__ out) {
    extern __shared__ __align__(1024) char smem[];
    const int tid = threadIdx.x;
    const int bm = blockIdx.y, bn = blockIdx.x;

    int br = 0, wsel = 3;
    if (SPIKE) { br = blockIdx.z / 3; wsel = blockIdx.z % 3; }

    const __nv_bfloat16* pt[6];
#pragma unroll
    for (int s = 0; s < 3; ++s) {
        pt[s] = (SPIKE ? g_as[br][s] : g_xms[s]) + (size_t)(bm * 128) * CDIM;
        pt[3 + s] = g_ws[wsel][s] + (size_t)(bn * 128) * CDIM;
    }

#if TC_OK
    const uint32_t sbase = smem_u32(smem);
    const int wid = tid >> 5, lid = tid & 31;

    int rcoff[4];
    uint32_t soff[4];
#pragma unroll
    for (int i = 0; i < 4; ++i) {
        const int idx = tid + i * 256;
        const int r = idx >> 3, cw = idx & 7;
        rcoff[i] = r * CDIM + cw * 8;
        const uint32_t bo = r * 128 + cw * 16;
        soff[i] = bo ^ ((bo >> 3) & 0x70);
    }

    if (wid == 0) {
        asm volatile("tcgen05.alloc.cta_group::1.sync.aligned.shared::cta.b32 [%0], %1;"
                     :: "r"(sbase), "r"(128u) : "memory");
        asm volatile("tcgen05.relinquish_alloc_permit.cta_group::1.sync.aligned;");
    }
    if (tid == 0) {
        asm volatile("mbarrier.init.shared.b64 [%0], 1;" :: "r"(sbase + 16) : "memory");
        asm volatile("mbarrier.init.shared.b64 [%0], 1;" :: "r"(sbase + 24) : "memory");
    }
    __syncthreads();
    uint32_t tmem;
    asm volatile("ld.shared.b32 %0, [%1];" : "=r"(tmem) : "r"(sbase));

#pragma unroll
    for (int ti = 0; ti < 6; ++ti) {
#pragma unroll
        for (int i = 0; i < 4; ++i) {
            uint4 v = *(const uint4*)(pt[ti] + rcoff[i]);
            *(uint4*)(smem + CTRLB + ti * TILEB + soff[i]) = v;
        }
    }
    asm volatile("tcgen05.fence::before_thread_sync;" ::: "memory");
    __syncthreads();

    int ph0 = 0, ph1 = 0;
    uint4 pf[24];

    for (int c = 0; c < NCHUNK; ++c) {
        if (c + 1 < NCHUNK) {
            const int kt = (c + 1) * BKC;
#pragma unroll
            for (int ti = 0; ti < 6; ++ti)
#pragma unroll
                for (int i = 0; i < 4; ++i)
                    pf[ti * 4 + i] = *(const uint4*)(pt[ti] + kt + rcoff[i]);
        }

        if (wid == 0 && elect1()) {
            asm volatile("fence.proxy.async.shared::cta;" ::: "memory");
            asm volatile("tcgen05.fence::after_thread_sync;" ::: "memory");
            const uint32_t ab = sbase + CTRLB + (uint32_t)(c & 1) * STAGEB;
            const int PA[6] = {0, 0, 1, 0, 2, 1};
            const int PB[6] = {0, 1, 0, 2, 0, 1};
#pragma unroll
            for (int p = 0; p < 6; ++p) {
                const uint64_t ad = mkdesc(ab + PA[p] * TILEB);
                const uint64_t bd = mkdesc(ab + (3 + PB[p]) * TILEB);
#pragma unroll
                for (int nh = 0; nh < 2; ++nh) {
#pragma unroll
                    for (int ks = 0; ks < 4; ++ks) {
                        const uint32_t en = (c == 0 && p == 0 && ks == 0) ? 0u : 1u;
                        mma_ss(tmem + nh * 64, ad + ks * 2,
                               bd + nh * 512 + ks * 2, en);
                    }
                }
            }
            const uint32_t mb = sbase + 16 + (uint32_t)(c & 1) * 8;
            asm volatile(
                "tcgen05.commit.cta_group::1.mbarrier::arrive::one.shared::cluster.b64 [%0];"
                :: "r"(mb) : "memory");
        }

        if (c >= 1) {
            const int pi = (c - 1) & 1;
            mbwait(sbase + 16 + pi * 8, pi ? ph1 : ph0);
            if (pi) ph1 ^= 1; else ph0 ^= 1;
        }

        if (c + 1 < NCHUNK) {
            char* sb = smem + CTRLB + (size_t)((c + 1) & 1) * STAGEB;
#pragma unroll
            for (int ti = 0; ti < 6; ++ti)
#pragma unroll
                for (int i = 0; i < 4; ++i)
                    *(uint4*)(sb + ti * TILEB + soff[i]) = pf[ti * 4 + i];
            asm volatile("tcgen05.fence::before_thread_sync;" ::: "memory");
        }
        __syncthreads();
    }

    mbwait(sbase + 24, ph1);
    asm volatile("tcgen05.fence::after_thread_sync;" ::: "memory");

    if (wid < 4) {
        const int row = bm * 128 + wid * 32 + lid;
#pragma unroll
        for (int cb = 0; cb < 128; cb += 32) {
            uint32_t rg[32];
            LDTM32(rg, tmem + cb);
            asm volatile("tcgen05.wait::ld.sync.aligned;" ::: "memory");
            if (SPIKE) {
                uint32_t pk[16];
#pragma unroll
                for (int jj = 0; jj < 16; ++jj) {
                    const int col0 = bn * 128 + cb + jj * 2;
                    const unsigned e0 =
                        ((unsigned)blockIdx.z << 22) | ((unsigned)row << 11) | (unsigned)col0;
                    const unsigned m0 = mask_or_flag(__uint_as_float(rg[jj * 2 + 0]), e0);
                    const unsigned m1 = mask_or_flag(__uint_as_float(rg[jj * 2 + 1]), e0 + 1);
                    pk[jj] = m0 | (m1 << 16);
                }
                uint4* dst = (uint4*)&g_masks[blockIdx.z][(size_t)row * CDIM + bn * 128 + cb];
#pragma unroll
                for (int q = 0; q < 4; ++q)
                    dst[q] = make_uint4(pk[q * 4], pk[q * 4 + 1], pk[q * 4 + 2], pk[q * 4 + 3]);
            } else {
                float4* dst = (float4*)&out[(size_t)row * CDIM + bn * 128 + cb];
#pragma unroll
                for (int q = 0; q < 8; ++q)
                    dst[q] = make_float4(__uint_as_float(rg[q * 4]),
                                         __uint_as_float(rg[q * 4 + 1]),
                                         __uint_as_float(rg[q * 4 + 2]),
                                         __uint_as_float(rg[q * 4 + 3]));
            }
        }
    }
    __syncthreads();
    if (tid == 0) {
        asm volatile("mbarrier.inval.shared.b64 [%0];" :: "r"(sbase + 16) : "memory");
        asm volatile("mbarrier.inval.shared.b64 [%0];" :: "r"(sbase + 24) : "memory");
    }
    __syncthreads();
    if (wid == 0)
        asm volatile("tcgen05.dealloc.cta_group::1.sync.aligned.b32 %0, %1;"
                     :: "r"(tmem), "r"(128u));
#else
    // FFMA fallback (plain sm_103 pass)
    float (*As)[128] = (float (*)[128])smem;
    float (*Bs)[128] = (float (*)[128])(smem + 16 * 128 * 4);

    float acc[8][8];
#pragma unroll
    for (int i = 0; i < 8; ++i)
#pragma unroll
        for (int j = 0; j < 8; ++j) acc[i][j] = 0.f;

    const int ty = tid >> 4, tx = tid & 15;
    const int aRow = tid >> 2, aCol = (tid & 3) * 4;
    const int bN = tid & 127, bKh = (tid >> 7) * 8;

    for (int kt = 0; kt < CDIM; kt += 16) {
#pragma unroll
        for (int r = 0; r < 128; r += 64) {
            const size_t go = (size_t)(aRow + r) * CDIM + kt + aCol;
            float av[4] = {0.f, 0.f, 0.f, 0.f};
#pragma unroll
            for (int s = 0; s < 3; ++s) {
                union { uint2 u; __nv_bfloat16 h[4]; } ld;
                ld.u = *(const uint2*)(pt[s] + go);
#pragma unroll
                for (int e = 0; e < 4; ++e) av[e] += __bfloat162float(ld.h[e]);
            }
#pragma unroll
            for (int e = 0; e < 4; ++e) As[aCol + e][aRow + r] = av[e];
        }
        {
            const size_t go = (size_t)bN * CDIM + kt + bKh;
            float bv[8] = {0.f, 0.f, 0.f, 0.f, 0.f, 0.f, 0.f, 0.f};
#pragma unroll
            for (int s = 0; s < 3; ++s) {
                union { uint4 u; __nv_bfloat16 h[8]; } ld;
                ld.u = *(const uint4*)(pt[3 + s] + go);
#pragma unroll
                for (int e = 0; e < 8; ++e) bv[e] += __bfloat162float(ld.h[e]);
            }
#pragma unroll
            for (int e = 0; e < 8; ++e) Bs[bKh + e][bN] = bv[e];
        }
        __syncthreads();

#pragma unroll
        for (int k = 0; k < 16; ++k) {
            float ra[8], rb[8];
#pragma unroll
            for (int i = 0; i < 8; ++i) ra[i] = As[k][ty * 8 + i];
#pragma unroll
            for (int j = 0; j < 8; ++j) rb[j] = Bs[k][tx * 8 + j];
#pragma unroll
            for (int i = 0; i < 8; ++i)
#pragma unroll
                for (int j = 0; j < 8; ++j)
                    acc[i][j] = fmaf(ra[i], rb[j], acc[i][j]);
        }
        __syncthreads();
    }

    if (SPIKE) {
        unsigned short* Mo = g_masks[blockIdx.z];
#pragma unroll
        for (int i = 0; i < 8; ++i) {
            const int row = bm * 128 + ty * 8 + i;
#pragma unroll
            for (int j = 0; j < 8; ++j) {
                const int col = bn * 128 + tx * 8 + j;
                const unsigned enc =
                    ((unsigned)blockIdx.z << 22) | ((unsigned)row << 11) | (unsigned)col;
                Mo[(size_t)row * CDIM + col] =
                    (unsigned short)mask_or_flag(acc[i][j], enc);
            }
        }
    } else {
#pragma unroll
        for (int i = 0; i < 8; ++i) {
            const int row = bm * 128 + ty * 8 + i;
#pragma unroll
            for (int j = 0; j < 8; ++j)
                out[(size_t)row * CDIM + bn * 128 + tx * 8 + j] = acc[i][j];
        }
    }
#endif
}

// ---------------------------------------------------------------------------
// Repair: one THREAD per flagged element. Strictly-sequential ascending-k
// fp32 fmaf chain — the summation order that round 3 proved reference-exact
// (zero flips at 9.4e-7). This makes repaired masks match the reference.
// ---------------------------------------------------------------------------
__global__ __launch_bounds__(256) void repair(const float* __restrict__ x) {
    const unsigned total = min(g_flagcnt, FLAG_CAP);
    for (unsigned e = blockIdx.x * 256 + threadIdx.x; e < total;
         e += gridDim.x * 256) {
        const unsigned enc = g_flags[e];
        const int z = enc >> 22;
        const int row = (enc >> 11) & 2047;
        const int col = enc & 2047;
        const int br = z / 3, ws = z % 3;
        const float4* xr = (const float4*)(x + (size_t)row * CDIM);
        const float4* wr = (const float4*)(g_wt[ws] + (size_t)col * CDIM);
        float acc = 0.f;
#pragma unroll 4
        for (int k4 = 0; k4 < CDIM / 4; ++k4) {
            const float4 a = xr[k4];
            const float4 b = wr[k4];
            float a0, a1, a2, a3;
            if (br) {
                a0 = fmaxf(-a.x, 0.f); a1 = fmaxf(-a.y, 0.f);
                a2 = fmaxf(-a.z, 0.f); a3 = fmaxf(-a.w, 0.f);
            } else {
                a0 = fmaxf(a.x, 0.f); a1 = fmaxf(a.y, 0.f);
                a2 = fmaxf(a.z, 0.f); a3 = fmaxf(a.w, 0.f);
            }
            acc = fmaf(a0, b.x, acc);
            acc = fmaf(a1, b.y, acc);
            acc = fmaf(a2, b.z, acc);
            acc = fmaf(a3, b.w, acc);
        }
        g_masks[z][(size_t)row * CDIM + col] = (unsigned short)if_scan_mask(acc);
    }
}

// ---------------------------------------------------------------------------
// Per-token spiking attention; writes Xm bf16 splits (for emulated out-GEMM).
// ---------------------------------------------------------------------------
__global__ __launch_bounds__(256) void attn_k() {
    const int n = blockIdx.x;
    const int tid = threadIdx.x;

    __shared__ unsigned short Mp[3][CDIM];
    __shared__ unsigned short Mn[3][CDIM];
    __shared__ __align__(16) int8_t Qt[CDIM];
    __shared__ __align__(16) int8_t Kt[CDIM];
    __shared__ __align__(16) int8_t Vt[CDIM];
    __shared__ int attn_s[HEADS * HEADS];

    const size_t base = (size_t)n * CDIM;
    for (int c = tid; c < CDIM; c += 256) {
        Mp[0][c] = g_masks[0][base + c];
        Mp[1][c] = g_masks[1][base + c];
        Mp[2][c] = g_masks[2][base + c];
        Mn[0][c] = g_masks[3][base + c];
        Mn[1][c] = g_masks[4][base + c];
        Mn[2][c] = g_masks[5][base + c];
    }
    __syncthreads();

    int acc[8];
#pragma unroll
    for (int j = 0; j < 8; ++j) acc[j] = 0;

    const int h = tid >> 4;
    const int dbase = (tid & 15) * 8;

    for (int t = 0; t < TSTEPS; ++t) {
        for (int c = tid; c < CDIM; c += 256) {
            Qt[c] = (int8_t)(((Mp[0][c] >> t) & 1) - ((Mn[0][c] >> t) & 1));
            Kt[c] = (int8_t)(((Mp[1][c] >> t) & 1) - ((Mn[1][c] >> t) & 1));
            Vt[c] = (int8_t)(((Mp[2][c] >> t) & 1) - ((Mn[2][c] >> t) & 1));
        }
        __syncthreads();

        {
            const int hh = tid >> 4;
            const int mm = tid & 15;
            const int* qr = (const int*)(Qt + hh * 128);
            const int* kr = (const int*)(Kt + mm * 128);
            const int rot = (mm * 2) & 31;
            int s = 0;
#pragma unroll
            for (int w = 0; w < 32; ++w) {
                const int wi = (w + rot) & 31;
                s = __dp4a(qr[wi], kr[wi], s);
            }
            attn_s[hh * 16 + mm] = s;
        }
        __syncthreads();

#pragma unroll
        for (int m = 0; m < HEADS; ++m) {
            const int a = attn_s[h * 16 + m];
            const int8_t* vp = Vt + m * 128 + dbase;
#pragma unroll
            for (int j = 0; j < 8; ++j) acc[j] += a * (int)vp[j];
        }
        __syncthreads();
    }

#pragma unroll
    for (int j = 0; j < 8; ++j) {
        const float val = (float)acc[j] * 0.0125f;
        __nv_bfloat16 h0, h1, h2;
        split3(val, h0, h1, h2);
        const size_t o = base + (size_t)(dbase + j) * HEADS + h;
        g_xms[0][o] = h0;
        g_xms[1][o] = h1;
        g_xms[2][o] = h2;
    }
}

// ---------------------------------------------------------------------------
extern "C" void kernel_launch(void* const* d_in, const int* in_sizes, int n_in,
                              void* d_out, int out_size) {
    const float* x  = (const float*)d_in[0];
    const float* wq = (const float*)d_in[2];
    const float* wk = (const float*)d_in[3];
    const float* wv = (const float*)d_in[4];
    const float* wo = (const float*)d_in[5];
    float* out = (float*)d_out;

    cudaFuncSetAttribute(gemm_tc<true>, cudaFuncAttributeMaxDynamicSharedMemorySize,
                         SMEM_TOTAL);
    cudaFuncSetAttribute(gemm_tc<false>, cudaFuncAttributeMaxDynamicSharedMemorySize,
                         SMEM_TOTAL);

    reset_flags<<<1, 1>>>();
    prep_x<<<(NDIM * CDIM) / (256 * 4), 256>>>(x);
    prep_w<<<dim3(64, 64, 4), dim3(32, 8)>>>(wq, wk, wv, wo);
    gemm_tc<true><<<dim3(16, 16, 6), 256, SMEM_TOTAL>>>(nullptr);
    repair<<<1184, 256>>>(x);
    attn_k<<<NDIM, 256>>>();
    gemm_tc<false><<<dim3(16, 16, 1), 256, SMEM_TOTAL>>>(out);
}

// round 13
// speedup vs baseline: 1.5698x; 1.1852x over previous
#include <cuda_runtime.h>
#include <cuda_bf16.h>
#include <stdint.h>

#define NDIM 2048
#define CDIM 2048
#define HEADS 16
#define TSTEPS 10

#define NCHUNK 32
#define BKC    64
#define TILEB  16384             // one tile: 128 rows x 128 bytes
#define STAGEB (4 * TILEB)       // 2 A-splits + 2 B-splits = 64KB
#define NSTAGE 3
#define CTRLB  1024
#define SMEM_TOTAL (CTRLB + NSTAGE * STAGEB)   // 197632

// idesc kind::f16, bf16 x bf16 -> f32, M=128, N=64
#define IDESC 0x8100490u

// Flag window: any |y_err| < DELTA is either provably maskless or repaired
// exactly. IF boundaries y=1/m are >= 1/90 apart >> 2*DELTA.
#define DELTA 5e-4f
#define FLAG_CAP (1u << 22)

#if defined(__CUDA_ARCH__) && \
    (defined(__CUDA_ARCH_FEAT_SM103_ALL) || defined(__CUDA_ARCH_FEAT_SM100_ALL) || \
     defined(__CUDA_ARCH_SPECIFIC__))
#define TC_OK 1
#else
#define TC_OK 0
#endif

// ---------------------------------------------------------------------------
// Global scratch
// ---------------------------------------------------------------------------
__device__ __align__(256) unsigned short g_masks[6][NDIM * CDIM];      // 48 MB
__device__ __align__(256) __nv_bfloat16 g_as[2][2][NDIM * CDIM];       // 32 MB
__device__ __align__(256) __nv_bfloat16 g_ws[4][2][CDIM * CDIM];       // 64 MB
__device__ __align__(256) float g_wt[3][CDIM * CDIM];                  // 48 MB fp32 wT (repair)
__device__ __align__(256) __nv_bfloat16 g_xms[2][NDIM * CDIM];         // 16 MB
__device__ unsigned g_flagcnt;
__device__ unsigned g_flags[FLAG_CAP];                                 // 16 MB

// ---------------------------------------------------------------------------
__device__ __forceinline__ void split2(float a, __nv_bfloat16& h0, __nv_bfloat16& h1) {
    h0 = __float2bfloat16_rn(a);
    h1 = __float2bfloat16_rn(a - __bfloat162float(h0));
}

__device__ __forceinline__ unsigned if_scan_mask(float y) {
    float v = 0.f;
    unsigned m = 0;
#pragma unroll
    for (int t = 0; t < TSTEPS; ++t) {
        v += y;
        if (v >= 1.0f) { m |= (1u << t); v = 0.f; }
    }
    return m;
}

// Provably-correct mask when the DELTA-interval crosses no IF boundary; else
// flag for exact sequential-order fp32 repair. Warp-aggregated atomic.
__device__ __forceinline__ unsigned mask_or_flag(float y, unsigned enc) {
    const unsigned mlo = if_scan_mask(y - DELTA);
    const unsigned mhi = if_scan_mask(y + DELTA);
    const bool flag = (mlo != mhi);
    const unsigned bal = __ballot_sync(0xFFFFFFFFu, flag);
    if (bal) {
        const int lane = threadIdx.x & 31;
        const int leader = __ffs(bal) - 1;
        unsigned base = 0;
        if (lane == leader) base = atomicAdd(&g_flagcnt, (unsigned)__popc(bal));
        base = __shfl_sync(0xFFFFFFFFu, base, leader);
        if (flag) {
            const unsigned off = (unsigned)__popc(bal & ((1u << lane) - 1u));
            if (base + off < FLAG_CAP) g_flags[base + off] = enc;
        }
    }
    return mlo;
}

#if TC_OK
// ---------------------------------------------------------------------------
// tcgen05-path PTX helpers
// ---------------------------------------------------------------------------
__device__ __forceinline__ uint32_t smem_u32(const void* p) {
    return (uint32_t)__cvta_generic_to_shared(p);
}
__device__ __forceinline__ uint32_t elect1() {
    uint32_t pred;
    asm volatile("{\n\t.reg .pred p;\n\telect.sync _|p, 0xFFFFFFFF;\n\t"
                 "selp.b32 %0, 1, 0, p;\n\t}" : "=r"(pred));
    return pred;
}
__device__ __forceinline__ uint64_t mkdesc(uint32_t addr) {
    return 0x4000404000010000ULL | (uint64_t)((addr >> 4) & 0x3FFF);
}
__device__ __forceinline__ void mma_ss(uint32_t d, uint64_t ad, uint64_t bd, uint32_t en) {
    asm volatile(
        "{\n\t.reg .pred p;\n\tsetp.ne.u32 p, %5, 0;\n\t"
        "tcgen05.mma.cta_group::1.kind::f16 [%0], %1, %2, %3, {%4, %4, %4, %4}, p;\n\t}"
        :: "r"(d), "l"(ad), "l"(bd), "r"(IDESC), "r"(0u), "r"(en) : "memory");
}
__device__ __forceinline__ void mbwait(uint32_t mb, int phase) {
    asm volatile(
        "{\n\t.reg .pred P;\n\tWL%=:\n\t"
        "mbarrier.try_wait.parity.acquire.cta.shared::cta.b64 P, [%0], %1, 0x989680;\n\t"
        "@P bra.uni WD%=;\n\tbra.uni WL%=;\n\tWD%=:\n\t}"
        :: "r"(mb), "r"(phase) : "memory");
}
#define LDTM32(r, addr) \
    asm volatile( \
        "tcgen05.ld.sync.aligned.32x32b.x32.b32 " \
        "{%0, %1, %2, %3, %4, %5, %6, %7, " \
        " %8, %9, %10, %11, %12, %13, %14, %15, " \
        " %16, %17, %18, %19, %20, %21, %22, %23, " \
        " %24, %25, %26, %27, %28, %29, %30, %31}, [%32];" \
        : "=r"((r)[0]),  "=r"((r)[1]),  "=r"((r)[2]),  "=r"((r)[3]), \
          "=r"((r)[4]),  "=r"((r)[5]),  "=r"((r)[6]),  "=r"((r)[7]), \
          "=r"((r)[8]),  "=r"((r)[9]),  "=r"((r)[10]), "=r"((r)[11]), \
          "=r"((r)[12]), "=r"((r)[13]), "=r"((r)[14]), "=r"((r)[15]), \
          "=r"((r)[16]), "=r"((r)[17]), "=r"((r)[18]), "=r"((r)[19]), \
          "=r"((r)[20]), "=r"((r)[21]), "=r"((r)[22]), "=r"((r)[23]), \
          "=r"((r)[24]), "=r"((r)[25]), "=r"((r)[26]), "=r"((r)[27]), \
          "=r"((r)[28]), "=r"((r)[29]), "=r"((r)[30]), "=r"((r)[31]) \
        : "r"(addr))
#endif  // TC_OK

// ---------------------------------------------------------------------------
__global__ void reset_flags() { g_flagcnt = 0; }

// prep_x: relu(+/-x) -> 2 bf16 splits each.
__global__ __launch_bounds__(256) void prep_x(const float* __restrict__ x) {
    const int i = blockIdx.x * 256 + threadIdx.x;
    float4 v = ((const float4*)x)[i];
    float p[4] = {fmaxf(v.x, 0.f), fmaxf(v.y, 0.f), fmaxf(v.z, 0.f), fmaxf(v.w, 0.f)};
    float n[4] = {fmaxf(-v.x, 0.f), fmaxf(-v.y, 0.f), fmaxf(-v.z, 0.f), fmaxf(-v.w, 0.f)};
    union U { __nv_bfloat16 h[4]; uint2 u; };
    U sp[2], sn[2];
#pragma unroll
    for (int e = 0; e < 4; ++e) {
        split2(p[e], sp[0].h[e], sp[1].h[e]);
        split2(n[e], sn[0].h[e], sn[1].h[e]);
    }
#pragma unroll
    for (int s = 0; s < 2; ++s) {
        ((uint2*)g_as[0][s])[i] = sp[s].u;
        ((uint2*)g_as[1][s])[i] = sn[s].u;
    }
}

// prep_w: transpose + 2-split wq,wk,wv,wo; fp32 wT for q,k,v (repair).
__global__ __launch_bounds__(256) void prep_w(const float* __restrict__ wq,
                                              const float* __restrict__ wk,
                                              const float* __restrict__ wv,
                                              const float* __restrict__ wo) {
    const int z = blockIdx.z;
    const float* w = (z == 0) ? wq : (z == 1) ? wk : (z == 2) ? wv : wo;
    __shared__ float tile[32][33];
    const int tx = threadIdx.x, ty = threadIdx.y;
    const int nBase = blockIdx.x * 32, kBase = blockIdx.y * 32;
#pragma unroll
    for (int i = 0; i < 4; ++i)
        tile[ty + i * 8][tx] = w[(size_t)(kBase + ty + i * 8) * CDIM + nBase + tx];
    __syncthreads();
#pragma unroll
    for (int i = 0; i < 4; ++i) {
        float v = tile[tx][ty + i * 8];
        __nv_bfloat16 h0, h1;
        split2(v, h0, h1);
        const size_t o = (size_t)(nBase + ty + i * 8) * CDIM + kBase + tx;
        g_ws[z][0][o] = h0;
        g_ws[z][1][o] = h1;
        if (z < 3) g_wt[z][o] = v;
    }
}

// ---------------------------------------------------------------------------
// tcgen05 bf16x3 emulated GEMM, 3-stage pipeline with decoupled LDG/STS.
// ---------------------------------------------------------------------------
template <bool SPIKE>
__global__ __launch_bounds__(256, 1) void gemm_tc(float* __restrict__ out) {
    extern __shared__ __align__(1024) char smem[];
    const int tid = threadIdx.x;
    const int bm = blockIdx.y, bn = blockIdx.x;

    int br = 0, wsel = 3;
    if (SPIKE) { br = blockIdx.z / 3; wsel = blockIdx.z % 3; }

    const __nv_bfloat16* pt[4];
#pragma unroll
    for (int s = 0; s < 2; ++s) {
        pt[s] = (SPIKE ? g_as[br][s] : g_xms[s]) + (size_t)(bm * 128) * CDIM;
        pt[2 + s] = g_ws[wsel][s] + (size_t)(bn * 128) * CDIM;
    }

#if TC_OK
    const uint32_t sbase = smem_u32(smem);
    const int wid = tid >> 5, lid = tid & 31;

    // per-thread slots: 4 x 16B per tile (1024 slots / 256 threads)
    int rcoff[4];
    uint32_t soff[4];
#pragma unroll
    for (int i = 0; i < 4; ++i) {
        const int idx = tid + i * 256;
        const int r = idx >> 3, cw = idx & 7;
        rcoff[i] = r * CDIM + cw * 8;
        const uint32_t bo = r * 128 + cw * 16;
        soff[i] = bo ^ ((bo >> 3) & 0x70);
    }

    if (wid == 0) {
        asm volatile("tcgen05.alloc.cta_group::1.sync.aligned.shared::cta.b32 [%0], %1;"
                     :: "r"(sbase), "r"(128u) : "memory");
        asm volatile("tcgen05.relinquish_alloc_permit.cta_group::1.sync.aligned;");
    }
    if (tid == 0) {
        asm volatile("mbarrier.init.shared.b64 [%0], 1;" :: "r"(sbase + 16) : "memory");
        asm volatile("mbarrier.init.shared.b64 [%0], 1;" :: "r"(sbase + 24) : "memory");
        asm volatile("mbarrier.init.shared.b64 [%0], 1;" :: "r"(sbase + 32) : "memory");
    }
    __syncthreads();
    uint32_t tmem;
    asm volatile("ld.shared.b32 %0, [%1];" : "=r"(tmem) : "r"(sbase));

    // Prologue: chunks 0,1 -> stages 0,1 (direct LDG+STS); chunk 2 -> pfA.
#pragma unroll
    for (int c0 = 0; c0 < 2; ++c0) {
        char* sb = smem + CTRLB + c0 * STAGEB;
#pragma unroll
        for (int ti = 0; ti < 4; ++ti)
#pragma unroll
            for (int i = 0; i < 4; ++i) {
                uint4 v = *(const uint4*)(pt[ti] + c0 * BKC + rcoff[i]);
                *(uint4*)(sb + ti * TILEB + soff[i]) = v;
            }
    }
    asm volatile("tcgen05.fence::before_thread_sync;" ::: "memory");
    __syncthreads();

    uint4 pfA[16], pfB[16];
#pragma unroll
    for (int ti = 0; ti < 4; ++ti)
#pragma unroll
        for (int i = 0; i < 4; ++i)
            pfA[ti * 4 + i] = *(const uint4*)(pt[ti] + 2 * BKC + rcoff[i]);

    int ph0 = 0, ph1 = 0, ph2 = 0;
    int scur = 0;   // stage of chunk c

#pragma unroll 1
    for (int c = 0; c < NCHUNK; ++c) {
        // (1) issue LDG for chunk c+3 into the buffer NOT being stored now
        if (c + 3 < NCHUNK) {
            const int kt = (c + 3) * BKC;
            if (c & 1) {
#pragma unroll
                for (int ti = 0; ti < 4; ++ti)
#pragma unroll
                    for (int i = 0; i < 4; ++i)
                        pfA[ti * 4 + i] = *(const uint4*)(pt[ti] + kt + rcoff[i]);
            } else {
#pragma unroll
                for (int ti = 0; ti < 4; ++ti)
#pragma unroll
                    for (int i = 0; i < 4; ++i)
                        pfB[ti * 4 + i] = *(const uint4*)(pt[ti] + kt + rcoff[i]);
            }
        }

        // (2) elect thread issues 24 MMAs for chunk c from stage scur
        if (wid == 0 && elect1()) {
            asm volatile("fence.proxy.async.shared::cta;" ::: "memory");
            asm volatile("tcgen05.fence::after_thread_sync;" ::: "memory");
            const uint32_t ab = sbase + CTRLB + (uint32_t)scur * STAGEB;
            const int PA[3] = {0, 0, 1};
            const int PB[3] = {0, 1, 0};
#pragma unroll
            for (int p = 0; p < 3; ++p) {
                const uint64_t ad = mkdesc(ab + PA[p] * TILEB);
                const uint64_t bd = mkdesc(ab + (2 + PB[p]) * TILEB);
#pragma unroll
                for (int nh = 0; nh < 2; ++nh) {
#pragma unroll
                    for (int ks = 0; ks < 4; ++ks) {
                        const uint32_t en = (c == 0 && p == 0 && ks == 0) ? 0u : 1u;
                        mma_ss(tmem + nh * 64, ad + ks * 2,
                               bd + nh * 512 + ks * 2, en);
                    }
                }
            }
            const uint32_t mb = sbase + 16 + (uint32_t)scur * 8;
            asm volatile(
                "tcgen05.commit.cta_group::1.mbarrier::arrive::one.shared::cluster.b64 [%0];"
                :: "r"(mb) : "memory");
        }

        // (3) wait chunk c-1 (its stage (c-1)%3 == (c+2)%3 is STS target below)
        const int pw = (scur == 0) ? 2 : scur - 1;
        if (c >= 1) {
            const int phase = (pw == 0) ? ph0 : (pw == 1) ? ph1 : ph2;
            mbwait(sbase + 16 + (uint32_t)pw * 8, phase);
            if (pw == 0) ph0 ^= 1; else if (pw == 1) ph1 ^= 1; else ph2 ^= 1;
        }

        // (4) STS chunk c+2 (loaded LAST iteration) into stage (c+2)%3 == pw
        if (c + 2 < NCHUNK) {
            char* sb = smem + CTRLB + (size_t)pw * STAGEB;
            const uint4* src = (c & 1) ? pfB : pfA;
#pragma unroll
            for (int ti = 0; ti < 4; ++ti)
#pragma unroll
                for (int i = 0; i < 4; ++i)
                    *(uint4*)(sb + ti * TILEB + soff[i]) = src[ti * 4 + i];
            asm volatile("tcgen05.fence::before_thread_sync;" ::: "memory");
        }
        __syncthreads();

        scur = (scur == 2) ? 0 : scur + 1;
    }

    // Drain: chunk 31 committed to mbar[31%3 = 1]
    mbwait(sbase + 16 + 8, ph1);
    asm volatile("tcgen05.fence::after_thread_sync;" ::: "memory");

    if (wid < 4) {
        const int row = bm * 128 + wid * 32 + lid;
#pragma unroll
        for (int cb = 0; cb < 128; cb += 32) {
            uint32_t rg[32];
            LDTM32(rg, tmem + cb);
            asm volatile("tcgen05.wait::ld.sync.aligned;" ::: "memory");
            if (SPIKE) {
                uint32_t pk[16];
#pragma unroll
                for (int jj = 0; jj < 16; ++jj) {
                    const int col0 = bn * 128 + cb + jj * 2;
                    const unsigned e0 =
                        ((unsigned)blockIdx.z << 22) | ((unsigned)row << 11) | (unsigned)col0;
                    const unsigned m0 = mask_or_flag(__uint_as_float(rg[jj * 2 + 0]), e0);
                    const unsigned m1 = mask_or_flag(__uint_as_float(rg[jj * 2 + 1]), e0 + 1);
                    pk[jj] = m0 | (m1 << 16);
                }
                uint4* dst = (uint4*)&g_masks[blockIdx.z][(size_t)row * CDIM + bn * 128 + cb];
#pragma unroll
                for (int q = 0; q < 4; ++q)
                    dst[q] = make_uint4(pk[q * 4], pk[q * 4 + 1], pk[q * 4 + 2], pk[q * 4 + 3]);
            } else {
                float4* dst = (float4*)&out[(size_t)row * CDIM + bn * 128 + cb];
#pragma unroll
                for (int q = 0; q < 8; ++q)
                    dst[q] = make_float4(__uint_as_float(rg[q * 4]),
                                         __uint_as_float(rg[q * 4 + 1]),
                                         __uint_as_float(rg[q * 4 + 2]),
                                         __uint_as_float(rg[q * 4 + 3]));
            }
        }
    }
    __syncthreads();
    if (tid == 0) {
        asm volatile("mbarrier.inval.shared.b64 [%0];" :: "r"(sbase + 16) : "memory");
        asm volatile("mbarrier.inval.shared.b64 [%0];" :: "r"(sbase + 24) : "memory");
        asm volatile("mbarrier.inval.shared.b64 [%0];" :: "r"(sbase + 32) : "memory");
    }
    __syncthreads();
    if (wid == 0)
        asm volatile("tcgen05.dealloc.cta_group::1.sync.aligned.b32 %0, %1;"
                     :: "r"(tmem), "r"(128u));
#else
    // FFMA fallback (plain sm_103 pass): recombine 2 splits.
    float (*As)[128] = (float (*)[128])smem;
    float (*Bs)[128] = (float (*)[128])(smem + 16 * 128 * 4);

    float acc[8][8];
#pragma unroll
    for (int i = 0; i < 8; ++i)
#pragma unroll
        for (int j = 0; j < 8; ++j) acc[i][j] = 0.f;

    const int ty = tid >> 4, tx = tid & 15;
    const int aRow = tid >> 2, aCol = (tid & 3) * 4;
    const int bN = tid & 127, bKh = (tid >> 7) * 8;

    for (int kt = 0; kt < CDIM; kt += 16) {
#pragma unroll
        for (int r = 0; r < 128; r += 64) {
            const size_t go = (size_t)(aRow + r) * CDIM + kt + aCol;
            float av[4] = {0.f, 0.f, 0.f, 0.f};
#pragma unroll
            for (int s = 0; s < 2; ++s) {
                union { uint2 u; __nv_bfloat16 h[4]; } ld;
                ld.u = *(const uint2*)(pt[s] + go);
#pragma unroll
                for (int e = 0; e < 4; ++e) av[e] += __bfloat162float(ld.h[e]);
            }
#pragma unroll
            for (int e = 0; e < 4; ++e) As[aCol + e][aRow + r] = av[e];
        }
        {
            const size_t go = (size_t)bN * CDIM + kt + bKh;
            float bv[8] = {0.f, 0.f, 0.f, 0.f, 0.f, 0.f, 0.f, 0.f};
#pragma unroll
            for (int s = 0; s < 2; ++s) {
                union { uint4 u; __nv_bfloat16 h[8]; } ld;
                ld.u = *(const uint4*)(pt[2 + s] + go);
#pragma unroll
                for (int e = 0; e < 8; ++e) bv[e] += __bfloat162float(ld.h[e]);
            }
#pragma unroll
            for (int e = 0; e < 8; ++e) Bs[bKh + e][bN] = bv[e];
        }
        __syncthreads();

#pragma unroll
        for (int k = 0; k < 16; ++k) {
            float ra[8], rb[8];
#pragma unroll
            for (int i = 0; i < 8; ++i) ra[i] = As[k][ty * 8 + i];
#pragma unroll
            for (int j = 0; j < 8; ++j) rb[j] = Bs[k][tx * 8 + j];
#pragma unroll
            for (int i = 0; i < 8; ++i)
#pragma unroll
                for (int j = 0; j < 8; ++j)
                    acc[i][j] = fmaf(ra[i], rb[j], acc[i][j]);
        }
        __syncthreads();
    }

    if (SPIKE) {
        unsigned short* Mo = g_masks[blockIdx.z];
#pragma unroll
        for (int i = 0; i < 8; ++i) {
            const int row = bm * 128 + ty * 8 + i;
#pragma unroll
            for (int j = 0; j < 8; ++j) {
                const int col = bn * 128 + tx * 8 + j;
                const unsigned enc =
                    ((unsigned)blockIdx.z << 22) | ((unsigned)row << 11) | (unsigned)col;
                Mo[(size_t)row * CDIM + col] =
                    (unsigned short)mask_or_flag(acc[i][j], enc);
            }
        }
    } else {
#pragma unroll
        for (int i = 0; i < 8; ++i) {
            const int row = bm * 128 + ty * 8 + i;
#pragma unroll
            for (int j = 0; j < 8; ++j)
                out[(size_t)row * CDIM + bn * 128 + tx * 8 + j] = acc[i][j];
        }
    }
#endif
}

// ---------------------------------------------------------------------------
// Repair: one THREAD per flagged element, strictly-sequential ascending-k
// fp32 fmaf chain (reference-exact summation order, proven in round 3/12).
// ---------------------------------------------------------------------------
__global__ __launch_bounds__(256) void repair(const float* __restrict__ x) {
    const unsigned total = min(g_flagcnt, FLAG_CAP);
    for (unsigned e = blockIdx.x * 256 + threadIdx.x; e < total;
         e += gridDim.x * 256) {
        const unsigned enc = g_flags[e];
        const int z = enc >> 22;
        const int row = (enc >> 11) & 2047;
        const int col = enc & 2047;
        const int br = z / 3, ws = z % 3;
        const float4* xr = (const float4*)(x + (size_t)row * CDIM);
        const float4* wr = (const float4*)(g_wt[ws] + (size_t)col * CDIM);
        float acc = 0.f;
#pragma unroll 4
        for (int k4 = 0; k4 < CDIM / 4; ++k4) {
            const float4 a = xr[k4];
            const float4 b = wr[k4];
            float a0, a1, a2, a3;
            if (br) {
                a0 = fmaxf(-a.x, 0.f); a1 = fmaxf(-a.y, 0.f);
                a2 = fmaxf(-a.z, 0.f); a3 = fmaxf(-a.w, 0.f);
            } else {
                a0 = fmaxf(a.x, 0.f); a1 = fmaxf(a.y, 0.f);
                a2 = fmaxf(a.z, 0.f); a3 = fmaxf(a.w, 0.f);
            }
            acc = fmaf(a0, b.x, acc);
            acc = fmaf(a1, b.y, acc);
            acc = fmaf(a2, b.z, acc);
            acc = fmaf(a3, b.w, acc);
        }
        g_masks[z][(size_t)row * CDIM + col] = (unsigned short)if_scan_mask(acc);
    }
}

// ---------------------------------------------------------------------------
// Per-token spiking attention; writes Xm bf16 2-splits (Xm exact in 16 bits).
// ---------------------------------------------------------------------------
__global__ __launch_bounds__(256) void attn_k() {
    const int n = blockIdx.x;
    const int tid = threadIdx.x;

    __shared__ unsigned short Mp[3][CDIM];
    __shared__ unsigned short Mn[3][CDIM];
    __shared__ __align__(16) int8_t Qt[CDIM];
    __shared__ __align__(16) int8_t Kt[CDIM];
    __shared__ __align__(16) int8_t Vt[CDIM];
    __shared__ int attn_s[HEADS * HEADS];

    const size_t base = (size_t)n * CDIM;
    for (int c = tid; c < CDIM; c += 256) {
        Mp[0][c] = g_masks[0][base + c];
        Mp[1][c] = g_masks[1][base + c];
        Mp[2][c] = g_masks[2][base + c];
        Mn[0][c] = g_masks[3][base + c];
        Mn[1][c] = g_masks[4][base + c];
        Mn[2][c] = g_masks[5][base + c];
    }
    __syncthreads();

    int acc[8];
#pragma unroll
    for (int j = 0; j < 8; ++j) acc[j] = 0;

    const int h = tid >> 4;
    const int dbase = (tid & 15) * 8;

    for (int t = 0; t < TSTEPS; ++t) {
        for (int c = tid; c < CDIM; c += 256) {
            Qt[c] = (int8_t)(((Mp[0][c] >> t) & 1) - ((Mn[0][c] >> t) & 1));
            Kt[c] = (int8_t)(((Mp[1][c] >> t) & 1) - ((Mn[1][c] >> t) & 1));
            Vt[c] = (int8_t)(((Mp[2][c] >> t) & 1) - ((Mn[2][c] >> t) & 1));
        }
        __syncthreads();

        {
            const int hh = tid >> 4;
            const int mm = tid & 15;
            const int* qr = (const int*)(Qt + hh * 128);
            const int* kr = (const int*)(Kt + mm * 128);
            const int rot = (mm * 2) & 31;
            int s = 0;
#pragma unroll
            for (int w = 0; w < 32; ++w) {
                const int wi = (w + rot) & 31;
                s = __dp4a(qr[wi], kr[wi], s);
            }
            attn_s[hh * 16 + mm] = s;
        }
        __syncthreads();

#pragma unroll
        for (int m = 0; m < HEADS; ++m) {
            const int a = attn_s[h * 16 + m];
            const int8_t* vp = Vt + m * 128 + dbase;
#pragma unroll
            for (int j = 0; j < 8; ++j) acc[j] += a * (int)vp[j];
        }
        __syncthreads();
    }

#pragma unroll
    for (int j = 0; j < 8; ++j) {
        const float val = (float)acc[j] * 0.0125f;
        __nv_bfloat16 h0, h1;
        split2(val, h0, h1);
        const size_t o = base + (size_t)(dbase + j) * HEADS + h;
        g_xms[0][o] = h0;
        g_xms[1][o] = h1;
    }
}

// ---------------------------------------------------------------------------
extern "C" void kernel_launch(void* const* d_in, const int* in_sizes, int n_in,
                              void* d_out, int out_size) {
    const float* x  = (const float*)d_in[0];
    const float* wq = (const float*)d_in[2];
    const float* wk = (const float*)d_in[3];
    const float* wv = (const float*)d_in[4];
    const float* wo = (const float*)d_in[5];
    float* out = (float*)d_out;

    cudaFuncSetAttribute(gemm_tc<true>, cudaFuncAttributeMaxDynamicSharedMemorySize,
                         SMEM_TOTAL);
    cudaFuncSetAttribute(gemm_tc<false>, cudaFuncAttributeMaxDynamicSharedMemorySize,
                         SMEM_TOTAL);

    reset_flags<<<1, 1>>>();
    prep_x<<<(NDIM * CDIM) / (256 * 4), 256>>>(x);
    prep_w<<<dim3(64, 64, 4), dim3(32, 8)>>>(wq, wk, wv, wo);
    gemm_tc<true><<<dim3(16, 16, 6), 256, SMEM_TOTAL>>>(nullptr);
    repair<<<1184, 256>>>(x);
    attn_k<<<NDIM, 256>>>();
    gemm_tc<false><<<dim3(16, 16, 1), 256, SMEM_TOTAL>>>(out);
}

// round 14
// speedup vs baseline: 1.6282x; 1.0372x over previous
#include <cuda_runtime.h>
#include <cuda.h>
#include <cuda_bf16.h>
#include <stdint.h>
#include <string.h>

#define NDIM 2048
#define CDIM 2048
#define HEADS 16
#define TSTEPS 10

#define NCHUNK 32
#define BKC    64
#define TILEB  16384             // one tile: 128 rows x 128 bytes
#define STAGEB (4 * TILEB)       // 2 A-splits + 2 B-splits = 64KB
#define NSTAGE 3
#define CTRLB  1024
#define SMEM_TOTAL (CTRLB + NSTAGE * STAGEB)   // 197632

// idesc kind::f16, bf16 x bf16 -> f32, M=128, N=64
#define IDESC 0x8100490u

// Flag window: any |y_err| < DELTA is either provably maskless or repaired
// exactly (sequential-order fp32). IF boundaries y=1/m are >= 1/90 apart.
#define DELTA 5e-4f
#define FLAG_CAP (1u << 22)

#if defined(__CUDA_ARCH__) && \
    (defined(__CUDA_ARCH_FEAT_SM103_ALL) || defined(__CUDA_ARCH_FEAT_SM100_ALL) || \
     defined(__CUDA_ARCH_SPECIFIC__))
#define TC_OK 1
#else
#define TC_OK 0
#endif

// Tensor maps passed by value (graph-capture safe, no device-side map copy).
struct Maps {
    CUtensorMap a[2][2];   // SPIKE: g_as[br][split]; OUT: a[0][split]=g_xms
    CUtensorMap b[3][2];   // SPIKE: g_ws[wsel][split]; OUT: b[0][split]=wo
};

// ---------------------------------------------------------------------------
// Global scratch
// ---------------------------------------------------------------------------
__device__ __align__(256) unsigned short g_masks[6][NDIM * CDIM];      // 48 MB
__device__ __align__(256) __nv_bfloat16 g_as[2][2][NDIM * CDIM];       // 32 MB
__device__ __align__(256) __nv_bfloat16 g_ws[4][2][CDIM * CDIM];       // 64 MB
__device__ __align__(256) float g_wt[3][CDIM * CDIM];                  // 48 MB
__device__ __align__(256) __nv_bfloat16 g_xms[2][NDIM * CDIM];         // 16 MB
__device__ unsigned g_flagcnt;
__device__ unsigned g_flags[FLAG_CAP];                                 // 16 MB

// ---------------------------------------------------------------------------
__device__ __forceinline__ void split2(float a, __nv_bfloat16& h0, __nv_bfloat16& h1) {
    h0 = __float2bfloat16_rn(a);
    h1 = __float2bfloat16_rn(a - __bfloat162float(h0));
}

__device__ __forceinline__ unsigned if_scan_mask(float y) {
    float v = 0.f;
    unsigned m = 0;
#pragma unroll
    for (int t = 0; t < TSTEPS; ++t) {
        v += y;
        if (v >= 1.0f) { m |= (1u << t); v = 0.f; }
    }
    return m;
}

__device__ __forceinline__ unsigned mask_or_flag(float y, unsigned enc) {
    const unsigned mlo = if_scan_mask(y - DELTA);
    const unsigned mhi = if_scan_mask(y + DELTA);
    const bool flag = (mlo != mhi);
    const unsigned bal = __ballot_sync(0xFFFFFFFFu, flag);
    if (bal) {
        const int lane = threadIdx.x & 31;
        const int leader = __ffs(bal) - 1;
        unsigned base = 0;
        if (lane == leader) base = atomicAdd(&g_flagcnt, (unsigned)__popc(bal));
        base = __shfl_sync(0xFFFFFFFFu, base, leader);
        if (flag) {
            const unsigned off = (unsigned)__popc(bal & ((1u << lane) - 1u));
            if (base + off < FLAG_CAP) g_flags[base + off] = enc;
        }
    }
    return mlo;
}

#if TC_OK
// ---------------------------------------------------------------------------
// tcgen05 / TMA PTX helpers (arch-specific pass only)
// ---------------------------------------------------------------------------
__device__ __forceinline__ uint32_t smem_u32(const void* p) {
    return (uint32_t)__cvta_generic_to_shared(p);
}
__device__ __forceinline__ uint64_t mkdesc(uint32_t addr) {
    return 0x4000404000010000ULL | (uint64_t)((addr >> 4) & 0x3FFF);
}
__device__ __forceinline__ void mma_ss(uint32_t d, uint64_t ad, uint64_t bd, uint32_t en) {
    asm volatile(
        "{\n\t.reg .pred p;\n\tsetp.ne.u32 p, %5, 0;\n\t"
        "tcgen05.mma.cta_group::1.kind::f16 [%0], %1, %2, %3, {%4, %4, %4, %4}, p;\n\t}"
        :: "r"(d), "l"(ad), "l"(bd), "r"(IDESC), "r"(0u), "r"(en) : "memory");
}
__device__ __forceinline__ void mbwait(uint32_t mb, int phase) {
    asm volatile(
        "{\n\t.reg .pred P;\n\tWL%=:\n\t"
        "mbarrier.try_wait.parity.acquire.cta.shared::cta.b64 P, [%0], %1, 0x989680;\n\t"
        "@P bra.uni WD%=;\n\tbra.uni WL%=;\n\tWD%=:\n\t}"
        :: "r"(mb), "r"(phase) : "memory");
}
__device__ __forceinline__ void tma2d(uint32_t dst, const CUtensorMap* map,
                                      int cx, int cy, uint32_t mbar) {
    asm volatile(
        "cp.async.bulk.tensor.2d.shared::cta.global.tile.mbarrier::complete_tx::bytes "
        "[%0], [%1, {%2, %3}], [%4];"
        :: "r"(dst), "l"(map), "r"(cx), "r"(cy), "r"(mbar) : "memory");
}
#define LDTM32(r, addr) \
    asm volatile( \
        "tcgen05.ld.sync.aligned.32x32b.x32.b32 " \
        "{%0, %1, %2, %3, %4, %5, %6, %7, " \
        " %8, %9, %10, %11, %12, %13, %14, %15, " \
        " %16, %17, %18, %19, %20, %21, %22, %23, " \
        " %24, %25, %26, %27, %28, %29, %30, %31}, [%32];" \
        : "=r"((r)[0]),  "=r"((r)[1]),  "=r"((r)[2]),  "=r"((r)[3]), \
          "=r"((r)[4]),  "=r"((r)[5]),  "=r"((r)[6]),  "=r"((r)[7]), \
          "=r"((r)[8]),  "=r"((r)[9]),  "=r"((r)[10]), "=r"((r)[11]), \
          "=r"((r)[12]), "=r"((r)[13]), "=r"((r)[14]), "=r"((r)[15]), \
          "=r"((r)[16]), "=r"((r)[17]), "=r"((r)[18]), "=r"((r)[19]), \
          "=r"((r)[20]), "=r"((r)[21]), "=r"((r)[22]), "=r"((r)[23]), \
          "=r"((r)[24]), "=r"((r)[25]), "=r"((r)[26]), "=r"((r)[27]), \
          "=r"((r)[28]), "=r"((r)[29]), "=r"((r)[30]), "=r"((r)[31]) \
        : "r"(addr))
#endif  // TC_OK

// ---------------------------------------------------------------------------
__global__ void reset_flags() { g_flagcnt = 0; }

__global__ __launch_bounds__(256) void prep_x(const float* __restrict__ x) {
    const int i = blockIdx.x * 256 + threadIdx.x;
    float4 v = ((const float4*)x)[i];
    float p[4] = {fmaxf(v.x, 0.f), fmaxf(v.y, 0.f), fmaxf(v.z, 0.f), fmaxf(v.w, 0.f)};
    float n[4] = {fmaxf(-v.x, 0.f), fmaxf(-v.y, 0.f), fmaxf(-v.z, 0.f), fmaxf(-v.w, 0.f)};
    union U { __nv_bfloat16 h[4]; uint2 u; };
    U sp[2], sn[2];
#pragma unroll
    for (int e = 0; e < 4; ++e) {
        split2(p[e], sp[0].h[e], sp[1].h[e]);
        split2(n[e], sn[0].h[e], sn[1].h[e]);
    }
#pragma unroll
    for (int s = 0; s < 2; ++s) {
        ((uint2*)g_as[0][s])[i] = sp[s].u;
        ((uint2*)g_as[1][s])[i] = sn[s].u;
    }
}

__global__ __launch_bounds__(256) void prep_w(const float* __restrict__ wq,
                                              const float* __restrict__ wk,
                                              const float* __restrict__ wv,
                                              const float* __restrict__ wo) {
    const int z = blockIdx.z;
    const float* w = (z == 0) ? wq : (z == 1) ? wk : (z == 2) ? wv : wo;
    __shared__ float tile[32][33];
    const int tx = threadIdx.x, ty = threadIdx.y;
    const int nBase = blockIdx.x * 32, kBase = blockIdx.y * 32;
#pragma unroll
    for (int i = 0; i < 4; ++i)
        tile[ty + i * 8][tx] = w[(size_t)(kBase + ty + i * 8) * CDIM + nBase + tx];
    __syncthreads();
#pragma unroll
    for (int i = 0; i < 4; ++i) {
        float v = tile[tx][ty + i * 8];
        __nv_bfloat16 h0, h1;
        split2(v, h0, h1);
        const size_t o = (size_t)(nBase + ty + i * 8) * CDIM + kBase + tx;
        g_ws[z][0][o] = h0;
        g_ws[z][1][o] = h1;
        if (z < 3) g_wt[z][o] = v;
    }
}

// ---------------------------------------------------------------------------
// tcgen05 bf16x3 emulated GEMM with TMA-fed 3-stage pipeline driven by one
// thread (full/empty mbarrier pairs; MMA commit = empty signal).
// ---------------------------------------------------------------------------
template <bool SPIKE>
__global__ __launch_bounds__(256, 1) void gemm_tc(const __grid_constant__ Maps maps,
                                                  float* __restrict__ out) {
    extern __shared__ __align__(1024) char smem[];
    const int tid = threadIdx.x;
    const int bm = blockIdx.y, bn = blockIdx.x;

    int br = 0, wsel = 0;
    if (SPIKE) { br = blockIdx.z / 3; wsel = blockIdx.z % 3; }

#if TC_OK
    const uint32_t sbase = smem_u32(smem);
    const int wid = tid >> 5, lid = tid & 31;

    if (wid == 0) {
        asm volatile("tcgen05.alloc.cta_group::1.sync.aligned.shared::cta.b32 [%0], %1;"
                     :: "r"(sbase), "r"(128u) : "memory");
        asm volatile("tcgen05.relinquish_alloc_permit.cta_group::1.sync.aligned;");
    }
    if (tid == 0) {
#pragma unroll
        for (int s = 0; s < NSTAGE; ++s) {
            asm volatile("mbarrier.init.shared.b64 [%0], 1;"
                         :: "r"(sbase + 16 + s * 8) : "memory");   // full[s]
            asm volatile("mbarrier.init.shared.b64 [%0], 1;"
                         :: "r"(sbase + 40 + s * 8) : "memory");   // empty[s]
        }
    }
    __syncthreads();
    uint32_t tmem;
    asm volatile("ld.shared.b32 %0, [%1];" : "=r"(tmem) : "r"(sbase));

    if (tid == 0) {
        const CUtensorMap* tmap[4] = {&maps.a[br][0], &maps.a[br][1],
                                      &maps.b[wsel][0], &maps.b[wsel][1]};
        const int cy[4] = {bm * 128, bm * 128, bn * 128, bn * 128};

        // Prologue: TMA chunks 0..2 into stages 0..2.
#pragma unroll
        for (int s = 0; s < NSTAGE; ++s) {
            const uint32_t fb = sbase + 16 + s * 8;
            asm volatile("mbarrier.arrive.expect_tx.shared.b64 _, [%0], %1;"
                         :: "r"(fb), "r"((unsigned)STAGEB) : "memory");
#pragma unroll
            for (int ti = 0; ti < 4; ++ti)
                tma2d(sbase + CTRLB + s * STAGEB + ti * TILEB, tmap[ti],
                      s * BKC, cy[ti], fb);
        }

        int phF[NSTAGE] = {0, 0, 0}, phE[NSTAGE] = {0, 0, 0};
        const int PA[3] = {0, 0, 1};
        const int PB[3] = {0, 1, 0};

#pragma unroll 1
        for (int c = 0; c < NCHUNK; ++c) {
            const int s = c % NSTAGE;
            mbwait(sbase + 16 + s * 8, phF[s]);
            phF[s] ^= 1;

            const uint32_t ab = sbase + CTRLB + (uint32_t)s * STAGEB;
#pragma unroll
            for (int p = 0; p < 3; ++p) {
                const uint64_t ad = mkdesc(ab + PA[p] * TILEB);
                const uint64_t bd = mkdesc(ab + (2 + PB[p]) * TILEB);
#pragma unroll
                for (int nh = 0; nh < 2; ++nh) {
#pragma unroll
                    for (int ks = 0; ks < 4; ++ks) {
                        const uint32_t en = (c == 0 && p == 0 && ks == 0) ? 0u : 1u;
                        mma_ss(tmem + nh * 64, ad + ks * 2,
                               bd + nh * 512 + ks * 2, en);
                    }
                }
            }
            asm volatile(
                "tcgen05.commit.cta_group::1.mbarrier::arrive::one.shared::cluster.b64 [%0];"
                :: "r"(sbase + 40 + s * 8) : "memory");

            // Reissue TMA for chunk (c-1)+NSTAGE into stage (c-1)%NSTAGE after
            // chunk c-1's MMAs complete (one-iteration lag keeps tensor busy).
            if (c >= 1) {
                const int cp = c - 1;
                if (cp + NSTAGE < NCHUNK) {
                    const int sp = cp % NSTAGE;
                    mbwait(sbase + 40 + sp * 8, phE[sp]);
                    phE[sp] ^= 1;
                    const uint32_t fb = sbase + 16 + sp * 8;
                    asm volatile("mbarrier.arrive.expect_tx.shared.b64 _, [%0], %1;"
                                 :: "r"(fb), "r"((unsigned)STAGEB) : "memory");
                    const int q = cp + NSTAGE;
#pragma unroll
                    for (int ti = 0; ti < 4; ++ti)
                        tma2d(sbase + CTRLB + sp * STAGEB + ti * TILEB, tmap[ti],
                              q * BKC, cy[ti], fb);
                }
            }
        }
        // Drain: chunk 31 (stage 1) — in-order tensor queue => all done.
        mbwait(sbase + 40 + ((NCHUNK - 1) % NSTAGE) * 8,
               phE[(NCHUNK - 1) % NSTAGE]);
    }
    __syncthreads();
    asm volatile("tcgen05.fence::after_thread_sync;" ::: "memory");

    if (wid < 4) {
        const int row = bm * 128 + wid * 32 + lid;
#pragma unroll
        for (int cb = 0; cb < 128; cb += 32) {
            uint32_t rg[32];
            LDTM32(rg, tmem + cb);
            asm volatile("tcgen05.wait::ld.sync.aligned;" ::: "memory");
            if (SPIKE) {
                uint32_t pk[16];
#pragma unroll
                for (int jj = 0; jj < 16; ++jj) {
                    const int col0 = bn * 128 + cb + jj * 2;
                    const unsigned e0 =
                        ((unsigned)blockIdx.z << 22) | ((unsigned)row << 11) | (unsigned)col0;
                    const unsigned m0 = mask_or_flag(__uint_as_float(rg[jj * 2 + 0]), e0);
                    const unsigned m1 = mask_or_flag(__uint_as_float(rg[jj * 2 + 1]), e0 + 1);
                    pk[jj] = m0 | (m1 << 16);
                }
                uint4* dst = (uint4*)&g_masks[blockIdx.z][(size_t)row * CDIM + bn * 128 + cb];
#pragma unroll
                for (int q = 0; q < 4; ++q)
                    dst[q] = make_uint4(pk[q * 4], pk[q * 4 + 1], pk[q * 4 + 2], pk[q * 4 + 3]);
            } else {
                float4* dst = (float4*)&out[(size_t)row * CDIM + bn * 128 + cb];
#pragma unroll
                for (int q = 0; q < 8; ++q)
                    dst[q] = make_float4(__uint_as_float(rg[q * 4]),
                                         __uint_as_float(rg[q * 4 + 1]),
                                         __uint_as_float(rg[q * 4 + 2]),
                                         __uint_as_float(rg[q * 4 + 3]));
            }
        }
    }
    __syncthreads();
    if (tid == 0) {
#pragma unroll
        for (int s = 0; s < NSTAGE; ++s) {
            asm volatile("mbarrier.inval.shared.b64 [%0];" :: "r"(sbase + 16 + s * 8) : "memory");
            asm volatile("mbarrier.inval.shared.b64 [%0];" :: "r"(sbase + 40 + s * 8) : "memory");
        }
    }
    __syncthreads();
    if (wid == 0)
        asm volatile("tcgen05.dealloc.cta_group::1.sync.aligned.b32 %0, %1;"
                     :: "r"(tmem), "r"(128u));
#else
    // FFMA fallback (plain sm_103 pass): recombine 2 splits, 256 threads.
    const __nv_bfloat16* pt[4];
#pragma unroll
    for (int s = 0; s < 2; ++s) {
        pt[s] = (SPIKE ? g_as[br][s] : g_xms[s]) + (size_t)(bm * 128) * CDIM;
        pt[2 + s] = g_ws[SPIKE ? wsel : 3][s] + (size_t)(bn * 128) * CDIM;
    }
    float (*As)[128] = (float (*)[128])smem;
    float (*Bs)[128] = (float (*)[128])(smem + 16 * 128 * 4);

    float acc[8][8];
#pragma unroll
    for (int i = 0; i < 8; ++i)
#pragma unroll
        for (int j = 0; j < 8; ++j) acc[i][j] = 0.f;

    const int ty = tid >> 4, tx = tid & 15;
    const int aRow = tid >> 2, aCol = (tid & 3) * 4;
    const int bN = tid & 127, bKh = (tid >> 7) * 8;

    for (int kt = 0; kt < CDIM; kt += 16) {
#pragma unroll
        for (int r = 0; r < 128; r += 64) {
            const size_t go = (size_t)(aRow + r) * CDIM + kt + aCol;
            float av[4] = {0.f, 0.f, 0.f, 0.f};
#pragma unroll
            for (int s = 0; s < 2; ++s) {
                union { uint2 u; __nv_bfloat16 h[4]; } ld;
                ld.u = *(const uint2*)(pt[s] + go);
#pragma unroll
                for (int e = 0; e < 4; ++e) av[e] += __bfloat162float(ld.h[e]);
            }
#pragma unroll
            for (int e = 0; e < 4; ++e) As[aCol + e][aRow + r] = av[e];
        }
        {
            const size_t go = (size_t)bN * CDIM + kt + bKh;
            float bv[8] = {0.f, 0.f, 0.f, 0.f, 0.f, 0.f, 0.f, 0.f};
#pragma unroll
            for (int s = 0; s < 2; ++s) {
                union { uint4 u; __nv_bfloat16 h[8]; } ld;
                ld.u = *(const uint4*)(pt[2 + s] + go);
#pragma unroll
                for (int e = 0; e < 8; ++e) bv[e] += __bfloat162float(ld.h[e]);
            }
#pragma unroll
            for (int e = 0; e < 8; ++e) Bs[bKh + e][bN] = bv[e];
        }
        __syncthreads();

#pragma unroll
        for (int k = 0; k < 16; ++k) {
            float ra[8], rb[8];
#pragma unroll
            for (int i = 0; i < 8; ++i) ra[i] = As[k][ty * 8 + i];
#pragma unroll
            for (int j = 0; j < 8; ++j) rb[j] = Bs[k][tx * 8 + j];
#pragma unroll
            for (int i = 0; i < 8; ++i)
#pragma unroll
                for (int j = 0; j < 8; ++j)
                    acc[i][j] = fmaf(ra[i], rb[j], acc[i][j]);
        }
        __syncthreads();
    }

    if (SPIKE) {
        unsigned short* Mo = g_masks[blockIdx.z];
#pragma unroll
        for (int i = 0; i < 8; ++i) {
            const int row = bm * 128 + ty * 8 + i;
#pragma unroll
            for (int j = 0; j < 8; ++j) {
                const int col = bn * 128 + tx * 8 + j;
                const unsigned enc =
                    ((unsigned)blockIdx.z << 22) | ((unsigned)row << 11) | (unsigned)col;
                Mo[(size_t)row * CDIM + col] =
                    (unsigned short)mask_or_flag(acc[i][j], enc);
            }
        }
    } else {
#pragma unroll
        for (int i = 0; i < 8; ++i) {
            const int row = bm * 128 + ty * 8 + i;
#pragma unroll
            for (int j = 0; j < 8; ++j)
                out[(size_t)row * CDIM + bn * 128 + tx * 8 + j] = acc[i][j];
        }
    }
#endif
}

// ---------------------------------------------------------------------------
// Repair: one thread per flagged element, strictly-sequential ascending-k
// fp32 fmaf chain (reference-exact summation order).
// ---------------------------------------------------------------------------
__global__ __launch_bounds__(256) void repair(const float* __restrict__ x) {
    const unsigned total = min(g_flagcnt, FLAG_CAP);
    for (unsigned e = blockIdx.x * 256 + threadIdx.x; e < total;
         e += gridDim.x * 256) {
        const unsigned enc = g_flags[e];
        const int z = enc >> 22;
        const int row = (enc >> 11) & 2047;
        const int col = enc & 2047;
        const int br = z / 3, ws = z % 3;
        const float4* xr = (const float4*)(x + (size_t)row * CDIM);
        const float4* wr = (const float4*)(g_wt[ws] + (size_t)col * CDIM);
        float acc = 0.f;
#pragma unroll 4
        for (int k4 = 0; k4 < CDIM / 4; ++k4) {
            const float4 a = xr[k4];
            const float4 b = wr[k4];
            float a0, a1, a2, a3;
            if (br) {
                a0 = fmaxf(-a.x, 0.f); a1 = fmaxf(-a.y, 0.f);
                a2 = fmaxf(-a.z, 0.f); a3 = fmaxf(-a.w, 0.f);
            } else {
                a0 = fmaxf(a.x, 0.f); a1 = fmaxf(a.y, 0.f);
                a2 = fmaxf(a.z, 0.f); a3 = fmaxf(a.w, 0.f);
            }
            acc = fmaf(a0, b.x, acc);
            acc = fmaf(a1, b.y, acc);
            acc = fmaf(a2, b.z, acc);
            acc = fmaf(a3, b.w, acc);
        }
        g_masks[z][(size_t)row * CDIM + col] = (unsigned short)if_scan_mask(acc);
    }
}

// ---------------------------------------------------------------------------
// Per-token spiking attention; writes Xm bf16 2-splits.
// ---------------------------------------------------------------------------
__global__ __launch_bounds__(256) void attn_k() {
    const int n = blockIdx.x;
    const int tid = threadIdx.x;

    __shared__ unsigned short Mp[3][CDIM];
    __shared__ unsigned short Mn[3][CDIM];
    __shared__ __align__(16) int8_t Qt[CDIM];
    __shared__ __align__(16) int8_t Kt[CDIM];
    __shared__ __align__(16) int8_t Vt[CDIM];
    __shared__ int attn_s[HEADS * HEADS];

    const size_t base = (size_t)n * CDIM;
    for (int c = tid; c < CDIM; c += 256) {
        Mp[0][c] = g_masks[0][base + c];
        Mp[1][c] = g_masks[1][base + c];
        Mp[2][c] = g_masks[2][base + c];
        Mn[0][c] = g_masks[3][base + c];
        Mn[1][c] = g_masks[4][base + c];
        Mn[2][c] = g_masks[5][base + c];
    }
    __syncthreads();

    int acc[8];
#pragma unroll
    for (int j = 0; j < 8; ++j) acc[j] = 0;

    const int h = tid >> 4;
    const int dbase = (tid & 15) * 8;

    for (int t = 0; t < TSTEPS; ++t) {
        for (int c = tid; c < CDIM; c += 256) {
            Qt[c] = (int8_t)(((Mp[0][c] >> t) & 1) - ((Mn[0][c] >> t) & 1));
            Kt[c] = (int8_t)(((Mp[1][c] >> t) & 1) - ((Mn[1][c] >> t) & 1));
            Vt[c] = (int8_t)(((Mp[2][c] >> t) & 1) - ((Mn[2][c] >> t) & 1));
        }
        __syncthreads();

        {
            const int hh = tid >> 4;
            const int mm = tid & 15;
            const int* qr = (const int*)(Qt + hh * 128);
            const int* kr = (const int*)(Kt + mm * 128);
            const int rot = (mm * 2) & 31;
            int s = 0;
#pragma unroll
            for (int w = 0; w < 32; ++w) {
                const int wi = (w + rot) & 31;
                s = __dp4a(qr[wi], kr[wi], s);
            }
            attn_s[hh * 16 + mm] = s;
        }
        __syncthreads();

#pragma unroll
        for (int m = 0; m < HEADS; ++m) {
            const int a = attn_s[h * 16 + m];
            const int8_t* vp = Vt + m * 128 + dbase;
#pragma unroll
            for (int j = 0; j < 8; ++j) acc[j] += a * (int)vp[j];
        }
        __syncthreads();
    }

#pragma unroll
    for (int j = 0; j < 8; ++j) {
        const float val = (float)acc[j] * 0.0125f;
        __nv_bfloat16 h0, h1;
        split2(val, h0, h1);
        const size_t o = base + (size_t)(dbase + j) * HEADS + h;
        g_xms[0][o] = h0;
        g_xms[1][o] = h1;
    }
}

// ---------------------------------------------------------------------------
typedef CUresult (*EncodeFn)(CUtensorMap*, CUtensorMapDataType, cuuint32_t, void*,
                             const cuuint64_t*, const cuuint64_t*, const cuuint32_t*,
                             const cuuint32_t*, CUtensorMapInterleave, CUtensorMapSwizzle,
                             CUtensorMapL2promotion, CUtensorMapFloatOOBfill);

static void build_map(EncodeFn enc, CUtensorMap* m, void* base) {
    cuuint64_t dims[2] = {CDIM, NDIM};            // inner (cols), rows
    cuuint64_t strides[1] = {CDIM * 2};           // row stride bytes
    cuuint32_t box[2] = {BKC, 128};               // 64 bf16 (=128B) x 128 rows
    cuuint32_t es[2] = {1, 1};
    enc(m, CU_TENSOR_MAP_DATA_TYPE_BFLOAT16, 2, base, dims, strides, box, es,
        CU_TENSOR_MAP_INTERLEAVE_NONE, CU_TENSOR_MAP_SWIZZLE_128B,
        CU_TENSOR_MAP_L2_PROMOTION_L2_128B, CU_TENSOR_MAP_FLOAT_OOB_FILL_NONE);
}

extern "C" void kernel_launch(void* const* d_in, const int* in_sizes, int n_in,
                              void* d_out, int out_size) {
    const float* x  = (const float*)d_in[0];
    const float* wq = (const float*)d_in[2];
    const float* wk = (const float*)d_in[3];
    const float* wv = (const float*)d_in[4];
    const float* wo = (const float*)d_in[5];
    float* out = (float*)d_out;

    // Resolve cuTensorMapEncodeTiled through the runtime (no -lcuda needed).
    EncodeFn enc = nullptr;
    cudaDriverEntryPointQueryResult qr;
    cudaGetDriverEntryPoint("cuTensorMapEncodeTiled", (void**)&enc,
                            cudaEnableDefault, &qr);

    void *pas = nullptr, *pws = nullptr, *pxms = nullptr;
    cudaGetSymbolAddress(&pas, g_as);
    cudaGetSymbolAddress(&pws, g_ws);
    cudaGetSymbolAddress(&pxms, g_xms);

    const size_t planeA = (size_t)NDIM * CDIM * 2;   // bytes per split plane
    const size_t planeW = (size_t)CDIM * CDIM * 2;

    Maps mS, mO;
    memset(&mS, 0, sizeof(mS));
    memset(&mO, 0, sizeof(mO));
    for (int br = 0; br < 2; ++br)
        for (int s = 0; s < 2; ++s)
            build_map(enc, &mS.a[br][s], (char*)pas + (br * 2 + s) * planeA);
    for (int z = 0; z < 3; ++z)
        for (int s = 0; s < 2; ++s)
            build_map(enc, &mS.b[z][s], (char*)pws + (z * 2 + s) * planeW);
    for (int s = 0; s < 2; ++s) {
        build_map(enc, &mO.a[0][s], (char*)pxms + s * planeA);
        build_map(enc, &mO.b[0][s], (char*)pws + (3 * 2 + s) * planeW);
    }

    cudaFuncSetAttribute(gemm_tc<true>, cudaFuncAttributeMaxDynamicSharedMemorySize,
                         SMEM_TOTAL);
    cudaFuncSetAttribute(gemm_tc<false>, cudaFuncAttributeMaxDynamicSharedMemorySize,
                         SMEM_TOTAL);

    reset_flags<<<1, 1>>>();
    prep_x<<<(NDIM * CDIM) / (256 * 4), 256>>>(x);
    prep_w<<<dim3(64, 64, 4), dim3(32, 8)>>>(wq, wk, wv, wo);
    gemm_tc<true><<<dim3(16, 16, 6), 256, SMEM_TOTAL>>>(mS, nullptr);
    repair<<<1184, 256>>>(x);
    attn_k<<<NDIM, 256>>>();
    gemm_tc<false><<<dim3(16, 16, 1), 256, SMEM_TOTAL>>>(mO, out);
}